// round 2
// baseline (speedup 1.0000x reference)
#include <cuda_runtime.h>

#define D 64
#define NMAX 100000

__device__ float g_H1[NMAX * D];
__device__ float g_AGG1[NMAX * D];
__device__ float g_H2[NMAX * D];

// flags[0]: edge_index is int64 (1) or int32 (0)
// flags[1]: mask elem kind: 0 = uint8, 1 = float32, 2 = int32
__device__ int g_flags[2];

// ---------------------------------------------------------------------------
// Dtype detection (1 thread, runs first; deterministic for fixed inputs)
// ---------------------------------------------------------------------------
__global__ void detect_kernel(const int* __restrict__ ei_words,
                              const unsigned int* __restrict__ mask_words) {
    if (threadIdx.x != 0 || blockIdx.x != 0) return;

    // edge_index: int64 values < 2^31 => odd int32 words are all zero
    int is64 = 1;
    for (int i = 0; i < 256; i++) {
        if (ei_words[2 * i + 1] != 0) { is64 = 0; break; }
    }
    g_flags[0] = is64;

    // mask: float32 words are 0x3F800000 or 0; uint8 words have bytes in {0,1}
    // with upper bytes set almost surely; int32 words are 0 or 1 only.
    int kind = 2;  // assume int32 (words 0/1) unless evidence otherwise
    for (int i = 0; i < 4096; i++) {
        unsigned int w = mask_words[i];
        if (w == 0x3F800000u) { kind = 1; break; }
        if ((w & 0xFFFFFF00u) != 0) { kind = 0; break; }
    }
    g_flags[1] = kind;
}

// ---------------------------------------------------------------------------
// Init: AGG1 = 0, OUT = broadcast(b2)
// ---------------------------------------------------------------------------
__global__ void init_kernel(float* __restrict__ agg1, float* __restrict__ out,
                            const float* __restrict__ b2, int n4) {
    int i = blockIdx.x * blockDim.x + threadIdx.x;
    if (i >= n4) return;
    ((float4*)agg1)[i] = make_float4(0.f, 0.f, 0.f, 0.f);
    int c4 = i & 15;  // 16 float4 groups per 64-wide row
    ((float4*)out)[i] = __ldg(&((const float4*)b2)[c4]);
}

__device__ __forceinline__ bool mask_at(const void* mask, long gi, int kind) {
    if (kind == 1) return ((const float*)mask)[gi] != 0.f;
    if (kind == 2) return ((const int*)mask)[gi] != 0;
    return ((const unsigned char*)mask)[gi] != 0;
}

// ---------------------------------------------------------------------------
// Fused GEMM: C[n_rows,64] = f(A) @ W
//   MODE 0: f(a) = mask ? a*2 : 0                      (dropout, layer 1 input)
//   MODE 1: f(a) = mask ? relu(a + bias[k])*2 : 0      (bias+relu+dropout, layer 2)
// BM=64, BN=64, BK=16, 256 threads, 4x4 microtile per thread.
// ---------------------------------------------------------------------------
template <int K, int MODE>
__global__ void gemm64(const float* __restrict__ A,
                       const void* __restrict__ mask,
                       const float* __restrict__ W,
                       const float* __restrict__ bias,
                       float* __restrict__ C, int n_rows) {
    __shared__ float As[16][68];
    __shared__ float Bs[16][64];
    __shared__ float sb[64];

    int tid = threadIdx.x;
    int mkind = g_flags[1];
    if (MODE == 1) {
        if (tid < 64) sb[tid] = bias[tid];
    }
    __syncthreads();

    int row0 = blockIdx.x * 64;
    int tm = tid >> 4;   // 0..15
    int tn = tid & 15;   // 0..15
    float acc[4][4] = {};

    for (int k0 = 0; k0 < K; k0 += 16) {
        #pragma unroll
        for (int i = 0; i < 4; i++) {
            int idx = tid + i * 256;
            int r = idx >> 4;
            int kk = idx & 15;
            int gr = row0 + r;
            float a = 0.f;
            if (gr < n_rows) {
                long gi = (long)gr * K + k0 + kk;
                float v = A[gi];
                if (MODE == 1) v = fmaxf(v + sb[k0 + kk], 0.f);
                a = mask_at(mask, gi, mkind) ? v * 2.f : 0.f;
            }
            As[kk][r] = a;
        }
        #pragma unroll
        for (int i = 0; i < 4; i++) {
            int idx = tid + i * 256;
            int kk = idx >> 6;
            int nn = idx & 63;
            Bs[kk][nn] = W[(k0 + kk) * 64 + nn];
        }
        __syncthreads();

        #pragma unroll
        for (int k = 0; k < 16; k++) {
            float4 a4 = *(const float4*)&As[k][tm * 4];
            float4 b4 = *(const float4*)&Bs[k][tn * 4];
            float av[4] = {a4.x, a4.y, a4.z, a4.w};
            float bv[4] = {b4.x, b4.y, b4.z, b4.w};
            #pragma unroll
            for (int i = 0; i < 4; i++)
                #pragma unroll
                for (int j = 0; j < 4; j++)
                    acc[i][j] = fmaf(av[i], bv[j], acc[i][j]);
        }
        __syncthreads();
    }

    #pragma unroll
    for (int i = 0; i < 4; i++) {
        int gr = row0 + tm * 4 + i;
        if (gr < n_rows) {
            float4 o = make_float4(acc[i][0], acc[i][1], acc[i][2], acc[i][3]);
            *(float4*)&C[(long)gr * 64 + tn * 4] = o;
        }
    }
}

// ---------------------------------------------------------------------------
// Edge scatter: out[dst] += H[src] * w.  One warp per edge, float2 per lane.
// ---------------------------------------------------------------------------
__global__ void scatter_kernel(const float* __restrict__ H,
                               const void* __restrict__ ei_raw,
                               const float* __restrict__ ew,
                               float* __restrict__ out, int n_edges) {
    int e = blockIdx.x * 8 + (threadIdx.x >> 5);
    if (e >= n_edges) return;
    int lane = threadIdx.x & 31;
    int s, d;
    if (g_flags[0]) {
        const long long* ei = (const long long*)ei_raw;
        s = (int)ei[e];
        d = (int)ei[n_edges + e];
    } else {
        const int* ei = (const int*)ei_raw;
        s = ei[e];
        d = ei[n_edges + e];
    }
    float w = __ldg(&ew[e]);
    float2 v = *(const float2*)&H[(long)s * 64 + lane * 2];
    float* o = out + (long)d * 64 + lane * 2;
    atomicAdd(o, v.x * w);
    atomicAdd(o + 1, v.y * w);
}

// ---------------------------------------------------------------------------
// inputs: x, edge_index(2xE), edge_weight, W1, b1, W2, b2, mask1, mask2
// ---------------------------------------------------------------------------
extern "C" void kernel_launch(void* const* d_in, const int* in_sizes, int n_in,
                              void* d_out, int out_size) {
    const float* x  = (const float*)d_in[0];
    const void* ei  = d_in[1];
    const float* ew = (const float*)d_in[2];
    const float* W1 = (const float*)d_in[3];
    const float* b1 = (const float*)d_in[4];
    const float* W2 = (const float*)d_in[5];
    const float* b2 = (const float*)d_in[6];
    const void* m1  = d_in[7];
    const void* m2  = d_in[8];
    float* out = (float*)d_out;

    int n_nodes = in_sizes[0] / 384;
    int n_edges = in_sizes[2];

    float *H1, *AGG1, *H2;
    cudaGetSymbolAddress((void**)&H1, g_H1);
    cudaGetSymbolAddress((void**)&AGG1, g_AGG1);
    cudaGetSymbolAddress((void**)&H2, g_H2);

    detect_kernel<<<1, 32>>>((const int*)ei, (const unsigned int*)m1);

    int n4 = n_nodes * 16;
    init_kernel<<<(n4 + 255) / 256, 256>>>(AGG1, out, b2, n4);

    int gb = (n_nodes + 63) / 64;
    gemm64<384, 0><<<gb, 256>>>(x, m1, W1, nullptr, H1, n_nodes);
    scatter_kernel<<<(n_edges + 7) / 8, 256>>>(H1, ei, ew, AGG1, n_edges);
    gemm64<64, 1><<<gb, 256>>>(AGG1, m2, W2, b1, H2, n_nodes);
    scatter_kernel<<<(n_edges + 7) / 8, 256>>>(H2, ei, ew, out, n_edges);
}

// round 3
// speedup vs baseline: 1.1652x; 1.1652x over previous
#include <cuda_runtime.h>

#define D 64
#define NMAX 100000

__device__ float g_H1[NMAX * D];
__device__ float g_AGG1[NMAX * D];
__device__ float g_H2[NMAX * D];

// flags[0]: edge_index is int64 (1) or int32 (0)
// flags[1]: mask elem kind: 0 = uint8, 1 = float32, 2 = int32
__device__ int g_flags[2];

// ---------------------------------------------------------------------------
// Dtype detection (1 thread, deterministic for fixed inputs)
// ---------------------------------------------------------------------------
__global__ void detect_kernel(const int* __restrict__ ei_words,
                              const unsigned int* __restrict__ mask_words) {
    if (threadIdx.x != 0 || blockIdx.x != 0) return;
    int is64 = 1;
    for (int i = 0; i < 256; i++) {
        if (ei_words[2 * i + 1] != 0) { is64 = 0; break; }
    }
    g_flags[0] = is64;

    int kind = 2;
    for (int i = 0; i < 4096; i++) {
        unsigned int w = mask_words[i];
        if (w == 0x3F800000u) { kind = 1; break; }
        if ((w & 0xFFFFFF00u) != 0) { kind = 0; break; }
    }
    g_flags[1] = kind;
}

// ---------------------------------------------------------------------------
// Init: AGG1 = 0, OUT = broadcast(b2)
// ---------------------------------------------------------------------------
__global__ void init_kernel(float* __restrict__ agg1, float* __restrict__ out,
                            const float* __restrict__ b2, int n4) {
    int i = blockIdx.x * blockDim.x + threadIdx.x;
    if (i >= n4) return;
    ((float4*)agg1)[i] = make_float4(0.f, 0.f, 0.f, 0.f);
    int c4 = i & 15;
    ((float4*)out)[i] = __ldg(&((const float4*)b2)[c4]);
}

__device__ __forceinline__ bool mask_at(const void* mask, long gi, int kind) {
    if (kind == 1) return ((const float*)mask)[gi] != 0.f;
    if (kind == 2) return ((const int*)mask)[gi] != 0;
    return ((const unsigned char*)mask)[gi] != 0;
}

// ---------------------------------------------------------------------------
// Fused GEMM: C[n_rows,64] = f(A) @ W
//   MODE 0: f(a) = mask ? a*2 : 0
//   MODE 1: f(a) = mask ? relu(a + bias[k])*2 : 0
// BM=128, BN=64, BK=16, 256 threads, 8x4 microtile per thread.
// ---------------------------------------------------------------------------
template <int K, int MODE>
__global__ __launch_bounds__(256) void gemm128(
        const float* __restrict__ A,
        const void* __restrict__ mask,
        const float* __restrict__ W,
        const float* __restrict__ bias,
        float* __restrict__ C, int n_rows) {
    __shared__ float As[16][132];   // [k][m], padded
    __shared__ float Bs[16][64];
    __shared__ float sb[64];

    int tid = threadIdx.x;
    int mkind = g_flags[1];
    if (MODE == 1) {
        if (tid < 64) sb[tid] = bias[tid];
    }
    __syncthreads();

    int row0 = blockIdx.x * 128;
    int tm = tid >> 4;   // 0..15  -> 8 rows each
    int tn = tid & 15;   // 0..15  -> 4 cols each
    float acc[8][4] = {};

    for (int k0 = 0; k0 < K; k0 += 16) {
        // A tile: 128 rows x 16 k, fused activation/dropout
        #pragma unroll
        for (int i = 0; i < 8; i++) {
            int idx = tid + i * 256;
            int r = idx >> 4;
            int kk = idx & 15;
            int gr = row0 + r;
            float a = 0.f;
            if (gr < n_rows) {
                long gi = (long)gr * K + k0 + kk;
                float v = A[gi];
                if (MODE == 1) v = fmaxf(v + sb[k0 + kk], 0.f);
                a = mask_at(mask, gi, mkind) ? v * 2.f : 0.f;
            }
            As[kk][r] = a;
        }
        // W tile: 16 k x 64 n, coalesced
        #pragma unroll
        for (int i = 0; i < 4; i++) {
            int idx = tid + i * 256;
            int kk = idx >> 6;
            int nn = idx & 63;
            Bs[kk][nn] = W[(k0 + kk) * 64 + nn];
        }
        __syncthreads();

        #pragma unroll
        for (int k = 0; k < 16; k++) {
            float4 a0 = *(const float4*)&As[k][tm * 8];
            float4 a1 = *(const float4*)&As[k][tm * 8 + 4];
            float4 b4 = *(const float4*)&Bs[k][tn * 4];
            float av[8] = {a0.x, a0.y, a0.z, a0.w, a1.x, a1.y, a1.z, a1.w};
            float bv[4] = {b4.x, b4.y, b4.z, b4.w};
            #pragma unroll
            for (int i = 0; i < 8; i++)
                #pragma unroll
                for (int j = 0; j < 4; j++)
                    acc[i][j] = fmaf(av[i], bv[j], acc[i][j]);
        }
        __syncthreads();
    }

    #pragma unroll
    for (int i = 0; i < 8; i++) {
        int gr = row0 + tm * 8 + i;
        if (gr < n_rows) {
            float4 o = make_float4(acc[i][0], acc[i][1], acc[i][2], acc[i][3]);
            *(float4*)&C[(long)gr * 64 + tn * 4] = o;
        }
    }
}

// ---------------------------------------------------------------------------
// Edge scatter: out[dst] += H[src] * w.
// 16 lanes per edge, float4 gather + red.global.add.v4.f32 (sm_90+).
// ---------------------------------------------------------------------------
__global__ __launch_bounds__(256) void scatter_kernel(
        const float* __restrict__ H,
        const void* __restrict__ ei_raw,
        const float* __restrict__ ew,
        float* __restrict__ out, int n_edges) {
    int e = blockIdx.x * 16 + (threadIdx.x >> 4);
    if (e >= n_edges) return;
    int c = (threadIdx.x & 15) * 4;
    int s, d;
    if (g_flags[0]) {
        const long long* ei = (const long long*)ei_raw;
        s = (int)__ldg(&ei[e]);
        d = (int)__ldg(&ei[n_edges + e]);
    } else {
        const int* ei = (const int*)ei_raw;
        s = __ldg(&ei[e]);
        d = __ldg(&ei[n_edges + e]);
    }
    float w = __ldg(&ew[e]);
    float4 v = __ldg((const float4*)&H[(long)s * 64 + c]);
    float* o = out + (long)d * 64 + c;
    asm volatile("red.global.add.v4.f32 [%0], {%1, %2, %3, %4};"
                 :: "l"(o), "f"(v.x * w), "f"(v.y * w), "f"(v.z * w), "f"(v.w * w)
                 : "memory");
}

// ---------------------------------------------------------------------------
// inputs: x, edge_index(2xE), edge_weight, W1, b1, W2, b2, mask1, mask2
// ---------------------------------------------------------------------------
extern "C" void kernel_launch(void* const* d_in, const int* in_sizes, int n_in,
                              void* d_out, int out_size) {
    const float* x  = (const float*)d_in[0];
    const void* ei  = d_in[1];
    const float* ew = (const float*)d_in[2];
    const float* W1 = (const float*)d_in[3];
    const float* b1 = (const float*)d_in[4];
    const float* W2 = (const float*)d_in[5];
    const float* b2 = (const float*)d_in[6];
    const void* m1  = d_in[7];
    const void* m2  = d_in[8];
    float* out = (float*)d_out;

    int n_nodes = in_sizes[0] / 384;
    int n_edges = in_sizes[2];

    float *H1, *AGG1, *H2;
    cudaGetSymbolAddress((void**)&H1, g_H1);
    cudaGetSymbolAddress((void**)&AGG1, g_AGG1);
    cudaGetSymbolAddress((void**)&H2, g_H2);

    detect_kernel<<<1, 32>>>((const int*)ei, (const unsigned int*)m1);

    int n4 = n_nodes * 16;
    init_kernel<<<(n4 + 255) / 256, 256>>>(AGG1, out, b2, n4);

    int gb = (n_nodes + 127) / 128;
    int sb = (n_edges + 15) / 16;
    gemm128<384, 0><<<gb, 256>>>(x, m1, W1, nullptr, H1, n_nodes);
    scatter_kernel<<<sb, 256>>>(H1, ei, ew, AGG1, n_edges);
    gemm128<64, 1><<<gb, 256>>>(AGG1, m2, W2, b1, H2, n_nodes);
    scatter_kernel<<<sb, 256>>>(H2, ei, ew, out, n_edges);
}

// round 5
// speedup vs baseline: 1.3154x; 1.1289x over previous
#include <cuda_runtime.h>

#define D 64
#define NMAX 100000

__device__ float g_H1[NMAX * D];
__device__ float g_AGG1[NMAX * D];
__device__ float g_H2[NMAX * D];

// flags[0]: edge_index is int64 (1) or int32 (0)
// flags[1]: mask elem kind: 0 = uint8, 1 = float32, 2 = int32
__device__ int g_flags[2];

// ---------------------------------------------------------------------------
// Dtype detection — warp-parallel, order-independent predicates.
// ---------------------------------------------------------------------------
__global__ void detect_kernel(const int* __restrict__ ei_words,
                              const unsigned int* __restrict__ mask_words) {
    int lane = threadIdx.x;

    int odd_nonzero = 0;
    #pragma unroll
    for (int i = 0; i < 8; i++) {
        if (ei_words[2 * (lane + i * 32) + 1] != 0) odd_nonzero = 1;
    }
    int is64 = !__any_sync(0xFFFFFFFFu, odd_nonzero);

    int saw_f32 = 0, saw_hi = 0;
    #pragma unroll
    for (int i = 0; i < 128; i++) {
        unsigned int w = mask_words[lane + i * 32];
        if (w == 0x3F800000u) saw_f32 = 1;
        if ((w & 0xFFFFFF00u) != 0) saw_hi = 1;
    }
    int any_f32 = __any_sync(0xFFFFFFFFu, saw_f32);
    int any_hi  = __any_sync(0xFFFFFFFFu, saw_hi);
    if (lane == 0) {
        g_flags[0] = is64;
        g_flags[1] = any_f32 ? 1 : (any_hi ? 0 : 2);
    }
}

// ---------------------------------------------------------------------------
// Init: AGG1 = 0, OUT = broadcast(b2)
// ---------------------------------------------------------------------------
__global__ void init_kernel(float* __restrict__ agg1, float* __restrict__ out,
                            const float* __restrict__ b2, int n4) {
    int i = blockIdx.x * blockDim.x + threadIdx.x;
    if (i >= n4) return;
    ((float4*)agg1)[i] = make_float4(0.f, 0.f, 0.f, 0.f);
    int c4 = i & 15;
    ((float4*)out)[i] = __ldg(&((const float4*)b2)[c4]);
}

// ---------------------------------------------------------------------------
// Fused GEMM: C[n_rows,64] = f(A) @ W
//   MODE 0: f(a) = mask ? a*2 : 0
//   MODE 1: f(a) = mask ? relu(a + bias[k])*2 : 0
// BM=128, BN=64, BK=16, 128 threads, 8x8 microtile per thread.
// ---------------------------------------------------------------------------
template <int K, int MODE>
__global__ __launch_bounds__(128) void gemm8x8(
        const float* __restrict__ A,
        const void* __restrict__ mask,
        const float* __restrict__ W,
        const float* __restrict__ bias,
        float* __restrict__ C, int n_rows) {
    __shared__ float As[16][136];   // [k][m], padded
    __shared__ float Bs[16][64];
    __shared__ float sb[64];

    int tid = threadIdx.x;
    int mkind = g_flags[1];
    if (MODE == 1) {
        if (tid < 64) sb[tid] = bias[tid];
        __syncthreads();
    }

    int row0 = blockIdx.x * 128;
    int tm = tid >> 3;   // 0..15 -> 8 rows each
    int tn = tid & 7;    // 0..7  -> 8 cols each
    float acc[8][8] = {};

    for (int k0 = 0; k0 < K; k0 += 16) {
        // A tile: 128 rows x 16 k. Each thread: 4 x (float4 + 4-wide mask).
        #pragma unroll
        for (int i = 0; i < 4; i++) {
            int lin = tid + i * 128;      // 0..511
            int r = lin >> 2;             // row 0..127
            int q = lin & 3;              // float4 within row-segment
            int gr = row0 + r;
            float4 v = make_float4(0.f, 0.f, 0.f, 0.f);
            if (gr < n_rows) {
                long gi = (long)gr * K + k0 + q * 4;
                v = *(const float4*)&A[gi];
                float mv[4];
                if (mkind == 0) {
                    unsigned int mw = *(const unsigned int*)((const unsigned char*)mask + gi);
                    mv[0] = (mw & 0x000000FFu) ? 2.f : 0.f;
                    mv[1] = (mw & 0x0000FF00u) ? 2.f : 0.f;
                    mv[2] = (mw & 0x00FF0000u) ? 2.f : 0.f;
                    mv[3] = (mw & 0xFF000000u) ? 2.f : 0.f;
                } else if (mkind == 1) {
                    float4 mf = *(const float4*)((const float*)mask + gi);
                    mv[0] = mf.x != 0.f ? 2.f : 0.f;
                    mv[1] = mf.y != 0.f ? 2.f : 0.f;
                    mv[2] = mf.z != 0.f ? 2.f : 0.f;
                    mv[3] = mf.w != 0.f ? 2.f : 0.f;
                } else {
                    int4 mi = *(const int4*)((const int*)mask + gi);
                    mv[0] = mi.x ? 2.f : 0.f;
                    mv[1] = mi.y ? 2.f : 0.f;
                    mv[2] = mi.z ? 2.f : 0.f;
                    mv[3] = mi.w ? 2.f : 0.f;
                }
                if (MODE == 1) {
                    v.x = fmaxf(v.x + sb[k0 + q * 4 + 0], 0.f);
                    v.y = fmaxf(v.y + sb[k0 + q * 4 + 1], 0.f);
                    v.z = fmaxf(v.z + sb[k0 + q * 4 + 2], 0.f);
                    v.w = fmaxf(v.w + sb[k0 + q * 4 + 3], 0.f);
                }
                v.x *= mv[0]; v.y *= mv[1]; v.z *= mv[2]; v.w *= mv[3];
            }
            As[q * 4 + 0][r] = v.x;
            As[q * 4 + 1][r] = v.y;
            As[q * 4 + 2][r] = v.z;
            As[q * 4 + 3][r] = v.w;
        }
        // W tile: 16 k x 64 n, float4 coalesced.  (Plain index — R4's bug was here.)
        #pragma unroll
        for (int i = 0; i < 2; i++) {
            int lin = tid + i * 128;      // 0..255
            int kk = lin >> 4;            // 0..15
            int n4 = lin & 15;            // 0..15
            *(float4*)&Bs[kk][n4 * 4] = *(const float4*)&W[(long)(k0 + kk) * 64 + n4 * 4];
        }
        __syncthreads();

        #pragma unroll
        for (int k = 0; k < 16; k++) {
            float4 a0 = *(const float4*)&As[k][tm * 8];
            float4 a1 = *(const float4*)&As[k][tm * 8 + 4];
            float4 b0 = *(const float4*)&Bs[k][tn * 8];
            float4 b1 = *(const float4*)&Bs[k][tn * 8 + 4];
            float av[8] = {a0.x, a0.y, a0.z, a0.w, a1.x, a1.y, a1.z, a1.w};
            float bv[8] = {b0.x, b0.y, b0.z, b0.w, b1.x, b1.y, b1.z, b1.w};
            #pragma unroll
            for (int i = 0; i < 8; i++)
                #pragma unroll
                for (int j = 0; j < 8; j++)
                    acc[i][j] = fmaf(av[i], bv[j], acc[i][j]);
        }
        __syncthreads();
    }

    #pragma unroll
    for (int i = 0; i < 8; i++) {
        int gr = row0 + tm * 8 + i;
        if (gr < n_rows) {
            *(float4*)&C[(long)gr * 64 + tn * 8]     = make_float4(acc[i][0], acc[i][1], acc[i][2], acc[i][3]);
            *(float4*)&C[(long)gr * 64 + tn * 8 + 4] = make_float4(acc[i][4], acc[i][5], acc[i][6], acc[i][7]);
        }
    }
}

// ---------------------------------------------------------------------------
// Edge scatter: out[dst] += H[src] * w.
// 16 lanes per edge, float4 gather + red.global.add.v4.f32.
// ---------------------------------------------------------------------------
__global__ __launch_bounds__(256) void scatter_kernel(
        const float* __restrict__ H,
        const void* __restrict__ ei_raw,
        const float* __restrict__ ew,
        float* __restrict__ out, int n_edges) {
    int e = blockIdx.x * 16 + (threadIdx.x >> 4);
    if (e >= n_edges) return;
    int c = (threadIdx.x & 15) * 4;
    int s, d;
    if (g_flags[0]) {
        const long long* ei = (const long long*)ei_raw;
        s = (int)__ldg(&ei[e]);
        d = (int)__ldg(&ei[n_edges + e]);
    } else {
        const int* ei = (const int*)ei_raw;
        s = __ldg(&ei[e]);
        d = __ldg(&ei[n_edges + e]);
    }
    float w = __ldg(&ew[e]);
    float4 v = __ldg((const float4*)&H[(long)s * 64 + c]);
    float* o = out + (long)d * 64 + c;
    asm volatile("red.global.add.v4.f32 [%0], {%1, %2, %3, %4};"
                 :: "l"(o), "f"(v.x * w), "f"(v.y * w), "f"(v.z * w), "f"(v.w * w)
                 : "memory");
}

// ---------------------------------------------------------------------------
// inputs: x, edge_index(2xE), edge_weight, W1, b1, W2, b2, mask1, mask2
// ---------------------------------------------------------------------------
extern "C" void kernel_launch(void* const* d_in, const int* in_sizes, int n_in,
                              void* d_out, int out_size) {
    const float* x  = (const float*)d_in[0];
    const void* ei  = d_in[1];
    const float* ew = (const float*)d_in[2];
    const float* W1 = (const float*)d_in[3];
    const float* b1 = (const float*)d_in[4];
    const float* W2 = (const float*)d_in[5];
    const float* b2 = (const float*)d_in[6];
    const void* m1  = d_in[7];
    const void* m2  = d_in[8];
    float* out = (float*)d_out;

    int n_nodes = in_sizes[0] / 384;
    int n_edges = in_sizes[2];

    float *H1, *AGG1, *H2;
    cudaGetSymbolAddress((void**)&H1, g_H1);
    cudaGetSymbolAddress((void**)&AGG1, g_AGG1);
    cudaGetSymbolAddress((void**)&H2, g_H2);

    detect_kernel<<<1, 32>>>((const int*)ei, (const unsigned int*)m1);

    int n4 = n_nodes * 16;
    init_kernel<<<(n4 + 255) / 256, 256>>>(AGG1, out, b2, n4);

    int gb = (n_nodes + 127) / 128;
    int sbk = (n_edges + 15) / 16;
    gemm8x8<384, 0><<<gb, 128>>>(x, m1, W1, nullptr, H1, n_nodes);
    scatter_kernel<<<sbk, 256>>>(H1, ei, ew, AGG1, n_edges);
    gemm8x8<64, 1><<<gb, 128>>>(AGG1, m2, W2, b1, H2, n_nodes);
    scatter_kernel<<<sbk, 256>>>(H2, ei, ew, out, n_edges);
}

// round 7
// speedup vs baseline: 1.8443x; 1.4021x over previous
#include <cuda_runtime.h>

#define D 64
#define NMAX 100000

__device__ float g_H1[NMAX * D];
__device__ float g_AGG1[NMAX * D];
__device__ float g_H2[NMAX * D];

// flags[0]: edge_index is int64 (1) or int32 (0)
// flags[1]: mask elem kind: 0 = uint8, 1 = float32, 2 = int32
__device__ int g_flags[2];

// ---------------------------------------------------------------------------
// Dtype detection — warp-parallel, order-independent predicates.
// ---------------------------------------------------------------------------
__global__ void detect_kernel(const int* __restrict__ ei_words,
                              const unsigned int* __restrict__ mask_words) {
    int lane = threadIdx.x;

    int odd_nonzero = 0;
    #pragma unroll
    for (int i = 0; i < 8; i++) {
        if (ei_words[2 * (lane + i * 32) + 1] != 0) odd_nonzero = 1;
    }
    int is64 = !__any_sync(0xFFFFFFFFu, odd_nonzero);

    int saw_f32 = 0, saw_hi = 0;
    #pragma unroll
    for (int i = 0; i < 128; i++) {
        unsigned int w = mask_words[lane + i * 32];
        if (w == 0x3F800000u) saw_f32 = 1;
        if ((w & 0xFFFFFF00u) != 0) saw_hi = 1;
    }
    int any_f32 = __any_sync(0xFFFFFFFFu, saw_f32);
    int any_hi  = __any_sync(0xFFFFFFFFu, saw_hi);
    if (lane == 0) {
        g_flags[0] = is64;
        g_flags[1] = any_f32 ? 1 : (any_hi ? 0 : 2);
    }
}

// ---------------------------------------------------------------------------
// Init: AGG1 = 0, OUT = broadcast(b2)
// ---------------------------------------------------------------------------
__global__ void init_kernel(float* __restrict__ agg1, float* __restrict__ out,
                            const float* __restrict__ b2, int n4) {
    int i = blockIdx.x * blockDim.x + threadIdx.x;
    if (i >= n4) return;
    ((float4*)agg1)[i] = make_float4(0.f, 0.f, 0.f, 0.f);
    int c4 = i & 15;
    ((float4*)out)[i] = __ldg(&((const float4*)b2)[c4]);
}

// ---------------------------------------------------------------------------
// Fused GEMM, double-buffered: C[n_rows,64] = f(A) @ W
//   MODE 0: f(a) = mask ? a*2 : 0
//   MODE 1: f(a) = mask ? relu(a + bias[k])*2 : 0
// BM=128, BN=64, BK=16, 128 threads, 8x8 microtile per thread.
// ---------------------------------------------------------------------------
template <int K, int MODE>
__global__ __launch_bounds__(128) void gemm8x8(
        const float* __restrict__ A,
        const void* __restrict__ mask,
        const float* __restrict__ W,
        const float* __restrict__ bias,
        float* __restrict__ C, int n_rows) {
    __shared__ float As[2][16][132];   // [buf][k][m]
    __shared__ float Bs[2][16][64];
    __shared__ float sb[64];

    const int tid = threadIdx.x;
    const int mkind = g_flags[1];
    if (MODE == 1) {
        if (tid < 64) sb[tid] = bias[tid];
        __syncthreads();   // sb is read by ALL threads in store_tile — R6's race was here
    }

    const int row0 = blockIdx.x * 128;
    const int tm = tid >> 3;   // 0..15 -> 8 rows each
    const int tn = tid & 7;    // 0..7  -> 8 cols each

    int arow[4], aq[4];
    #pragma unroll
    for (int i = 0; i < 4; i++) {
        int lin = tid + i * 128;
        arow[i] = lin >> 2;            // 0..127
        aq[i]   = lin & 3;             // float4 slot within 16-k row segment
    }
    int bkk[2], bn4[2];
    #pragma unroll
    for (int i = 0; i < 2; i++) {
        int lin = tid + i * 128;
        bkk[i] = lin >> 4;             // 0..15
        bn4[i] = lin & 15;             // 0..15
    }

    float4 ra[4];
    uint4  rm[4];
    float4 rb[2];

    auto load_tile = [&](int k0) {
        #pragma unroll
        for (int i = 0; i < 4; i++) {
            int gr = row0 + arow[i];
            ra[i] = make_float4(0.f, 0.f, 0.f, 0.f);
            rm[i] = make_uint4(0u, 0u, 0u, 0u);
            if (gr < n_rows) {
                long gi = (long)gr * K + k0 + aq[i] * 4;
                ra[i] = *(const float4*)&A[gi];
                if (mkind == 0) {
                    rm[i].x = *(const unsigned int*)((const unsigned char*)mask + gi);
                } else if (mkind == 1) {
                    float4 f = *(const float4*)((const float*)mask + gi);
                    rm[i] = make_uint4(__float_as_uint(f.x), __float_as_uint(f.y),
                                       __float_as_uint(f.z), __float_as_uint(f.w));
                } else {
                    rm[i] = *(const uint4*)((const int*)mask + gi);
                }
            }
        }
        #pragma unroll
        for (int i = 0; i < 2; i++)
            rb[i] = *(const float4*)&W[(long)(k0 + bkk[i]) * 64 + bn4[i] * 4];
    };

    auto store_tile = [&](int buf, int k0) {
        #pragma unroll
        for (int i = 0; i < 4; i++) {
            float4 v = ra[i];
            float mv[4];
            if (mkind == 0) {
                unsigned int mw = rm[i].x;
                mv[0] = (mw & 0x000000FFu) ? 2.f : 0.f;
                mv[1] = (mw & 0x0000FF00u) ? 2.f : 0.f;
                mv[2] = (mw & 0x00FF0000u) ? 2.f : 0.f;
                mv[3] = (mw & 0xFF000000u) ? 2.f : 0.f;
            } else {
                mv[0] = rm[i].x ? 2.f : 0.f;
                mv[1] = rm[i].y ? 2.f : 0.f;
                mv[2] = rm[i].z ? 2.f : 0.f;
                mv[3] = rm[i].w ? 2.f : 0.f;
            }
            if (MODE == 1) {
                int kb = k0 + aq[i] * 4;
                v.x = fmaxf(v.x + sb[kb + 0], 0.f);
                v.y = fmaxf(v.y + sb[kb + 1], 0.f);
                v.z = fmaxf(v.z + sb[kb + 2], 0.f);
                v.w = fmaxf(v.w + sb[kb + 3], 0.f);
            }
            int r = arow[i], q4 = aq[i] * 4;
            As[buf][q4 + 0][r] = v.x * mv[0];
            As[buf][q4 + 1][r] = v.y * mv[1];
            As[buf][q4 + 2][r] = v.z * mv[2];
            As[buf][q4 + 3][r] = v.w * mv[3];
        }
        #pragma unroll
        for (int i = 0; i < 2; i++)
            *(float4*)&Bs[buf][bkk[i]][bn4[i] * 4] = rb[i];
    };

    float acc[8][8] = {};
    const int NIT = K / 16;

    load_tile(0);
    store_tile(0, 0);
    __syncthreads();

    for (int it = 0; it < NIT; it++) {
        int cur = it & 1;
        if (it + 1 < NIT) load_tile((it + 1) * 16);

        #pragma unroll
        for (int k = 0; k < 16; k++) {
            float4 a0 = *(const float4*)&As[cur][k][tm * 8];
            float4 a1 = *(const float4*)&As[cur][k][tm * 8 + 4];
            float4 b0 = *(const float4*)&Bs[cur][k][tn * 8];
            float4 b1 = *(const float4*)&Bs[cur][k][tn * 8 + 4];
            float av[8] = {a0.x, a0.y, a0.z, a0.w, a1.x, a1.y, a1.z, a1.w};
            float bv[8] = {b0.x, b0.y, b0.z, b0.w, b1.x, b1.y, b1.z, b1.w};
            #pragma unroll
            for (int i = 0; i < 8; i++)
                #pragma unroll
                for (int j = 0; j < 8; j++)
                    acc[i][j] = fmaf(av[i], bv[j], acc[i][j]);
        }

        if (it + 1 < NIT) {
            store_tile(cur ^ 1, (it + 1) * 16);
            __syncthreads();
        }
    }

    #pragma unroll
    for (int i = 0; i < 8; i++) {
        int gr = row0 + tm * 8 + i;
        if (gr < n_rows) {
            *(float4*)&C[(long)gr * 64 + tn * 8]     = make_float4(acc[i][0], acc[i][1], acc[i][2], acc[i][3]);
            *(float4*)&C[(long)gr * 64 + tn * 8 + 4] = make_float4(acc[i][4], acc[i][5], acc[i][6], acc[i][7]);
        }
    }
}

// ---------------------------------------------------------------------------
// Edge scatter: out[dst] += H[src] * w.
// 16 lanes per edge, float4 gather + red.global.add.v4.f32.
// ---------------------------------------------------------------------------
__global__ __launch_bounds__(256) void scatter_kernel(
        const float* __restrict__ H,
        const void* __restrict__ ei_raw,
        const float* __restrict__ ew,
        float* __restrict__ out, int n_edges) {
    int e = blockIdx.x * 16 + (threadIdx.x >> 4);
    if (e >= n_edges) return;
    int c = (threadIdx.x & 15) * 4;
    int s, d;
    if (g_flags[0]) {
        const long long* ei = (const long long*)ei_raw;
        s = (int)__ldg(&ei[e]);
        d = (int)__ldg(&ei[n_edges + e]);
    } else {
        const int* ei = (const int*)ei_raw;
        s = __ldg(&ei[e]);
        d = __ldg(&ei[n_edges + e]);
    }
    float w = __ldg(&ew[e]);
    float4 v = __ldg((const float4*)&H[(long)s * 64 + c]);
    float* o = out + (long)d * 64 + c;
    asm volatile("red.global.add.v4.f32 [%0], {%1, %2, %3, %4};"
                 :: "l"(o), "f"(v.x * w), "f"(v.y * w), "f"(v.z * w), "f"(v.w * w)
                 : "memory");
}

// ---------------------------------------------------------------------------
// inputs: x, edge_index(2xE), edge_weight, W1, b1, W2, b2, mask1, mask2
// ---------------------------------------------------------------------------
extern "C" void kernel_launch(void* const* d_in, const int* in_sizes, int n_in,
                              void* d_out, int out_size) {
    const float* x  = (const float*)d_in[0];
    const void* ei  = d_in[1];
    const float* ew = (const float*)d_in[2];
    const float* W1 = (const float*)d_in[3];
    const float* b1 = (const float*)d_in[4];
    const float* W2 = (const float*)d_in[5];
    const float* b2 = (const float*)d_in[6];
    const void* m1  = d_in[7];
    const void* m2  = d_in[8];
    float* out = (float*)d_out;

    int n_nodes = in_sizes[0] / 384;
    int n_edges = in_sizes[2];

    float *H1, *AGG1, *H2;
    cudaGetSymbolAddress((void**)&H1, g_H1);
    cudaGetSymbolAddress((void**)&AGG1, g_AGG1);
    cudaGetSymbolAddress((void**)&H2, g_H2);

    detect_kernel<<<1, 32>>>((const int*)ei, (const unsigned int*)m1);

    int n4 = n_nodes * 16;
    init_kernel<<<(n4 + 255) / 256, 256>>>(AGG1, out, b2, n4);

    int gb = (n_nodes + 127) / 128;
    int sbk = (n_edges + 15) / 16;
    gemm8x8<384, 0><<<gb, 128>>>(x, m1, W1, nullptr, H1, n_nodes);
    scatter_kernel<<<sbk, 256>>>(H1, ei, ew, AGG1, n_edges);
    gemm8x8<64, 1><<<gb, 128>>>(AGG1, m2, W2, b1, H2, n_nodes);
    scatter_kernel<<<sbk, 256>>>(H2, ei, ew, out, n_edges);
}

// round 8
// speedup vs baseline: 2.1533x; 1.1675x over previous
#include <cuda_runtime.h>

#define D 64
#define NMAX 100000

__device__ float g_H1[NMAX * D];
__device__ float g_AGG1[NMAX * D];
__device__ float g_H2[NMAX * D];

// flags[0]: edge_index is int64 (1) or int32 (0)
// flags[1]: mask elem kind: 0 = uint8, 1 = float32, 2 = int32
__device__ int g_flags[2];

// ---- packed fp32x2 helpers (Blackwell sm_100+) ------------------------------
__device__ __forceinline__ unsigned long long pk2(float lo, float hi) {
    unsigned long long r;
    asm("mov.b64 %0, {%1, %2};" : "=l"(r) : "f"(lo), "f"(hi));
    return r;
}
__device__ __forceinline__ void upk2(float& lo, float& hi, unsigned long long v) {
    asm("mov.b64 {%0, %1}, %2;" : "=f"(lo), "=f"(hi) : "l"(v));
}
__device__ __forceinline__ unsigned long long ffma2(unsigned long long a,
                                                    unsigned long long b,
                                                    unsigned long long c) {
    unsigned long long d;
    asm("fma.rn.f32x2 %0, %1, %2, %3;" : "=l"(d) : "l"(a), "l"(b), "l"(c));
    return d;
}

// ---------------------------------------------------------------------------
// Dtype detection — warp-parallel, order-independent predicates.
// ---------------------------------------------------------------------------
__global__ void detect_kernel(const int* __restrict__ ei_words,
                              const unsigned int* __restrict__ mask_words) {
    int lane = threadIdx.x;

    int odd_nonzero = 0;
    #pragma unroll
    for (int i = 0; i < 8; i++) {
        if (ei_words[2 * (lane + i * 32) + 1] != 0) odd_nonzero = 1;
    }
    int is64 = !__any_sync(0xFFFFFFFFu, odd_nonzero);

    int saw_f32 = 0, saw_hi = 0;
    #pragma unroll
    for (int i = 0; i < 128; i++) {
        unsigned int w = mask_words[lane + i * 32];
        if (w == 0x3F800000u) saw_f32 = 1;
        if ((w & 0xFFFFFF00u) != 0) saw_hi = 1;
    }
    int any_f32 = __any_sync(0xFFFFFFFFu, saw_f32);
    int any_hi  = __any_sync(0xFFFFFFFFu, saw_hi);
    if (lane == 0) {
        g_flags[0] = is64;
        g_flags[1] = any_f32 ? 1 : (any_hi ? 0 : 2);
    }
}

// ---------------------------------------------------------------------------
// Init: AGG1 = 0, OUT = broadcast(b2)
// ---------------------------------------------------------------------------
__global__ void init_kernel(float* __restrict__ agg1, float* __restrict__ out,
                            const float* __restrict__ b2, int n4) {
    int i = blockIdx.x * blockDim.x + threadIdx.x;
    if (i >= n4) return;
    ((float4*)agg1)[i] = make_float4(0.f, 0.f, 0.f, 0.f);
    int c4 = i & 15;
    ((float4*)out)[i] = __ldg(&((const float4*)b2)[c4]);
}

// ---------------------------------------------------------------------------
// Fused GEMM, double-buffered, FFMA2 inner loop: C[n_rows,64] = f(A) @ W
//   MODE 0: f(a) = mask ? a*2 : 0
//   MODE 1: f(a) = mask ? relu(a + bias[k])*2 : 0
// BM=128, BN=64, BK=16, 128 threads, 8x8 microtile per thread.
// ---------------------------------------------------------------------------
template <int K, int MODE>
__global__ __launch_bounds__(128) void gemm8x8(
        const float* __restrict__ A,
        const void* __restrict__ mask,
        const float* __restrict__ W,
        const float* __restrict__ bias,
        float* __restrict__ C, int n_rows) {
    __shared__ float As[2][16][132];   // [buf][k][m]
    __shared__ float Bs[2][16][64];
    __shared__ float sb[64];

    const int tid = threadIdx.x;
    const int mkind = g_flags[1];
    if (MODE == 1) {
        if (tid < 64) sb[tid] = bias[tid];
        __syncthreads();   // sb read by ALL threads in store_tile
    }

    const int row0 = blockIdx.x * 128;
    const int tm = tid >> 3;   // 0..15 -> 8 rows each
    const int tn = tid & 7;    // 0..7  -> 8 cols each

    int arow[4], aq[4];
    #pragma unroll
    for (int i = 0; i < 4; i++) {
        int lin = tid + i * 128;
        arow[i] = lin >> 2;
        aq[i]   = lin & 3;
    }
    int bkk[2], bn4[2];
    #pragma unroll
    for (int i = 0; i < 2; i++) {
        int lin = tid + i * 128;
        bkk[i] = lin >> 4;
        bn4[i] = lin & 15;
    }

    float4 ra[4];
    uint4  rm[4];
    float4 rb[2];

    auto load_tile = [&](int k0) {
        #pragma unroll
        for (int i = 0; i < 4; i++) {
            int gr = row0 + arow[i];
            ra[i] = make_float4(0.f, 0.f, 0.f, 0.f);
            rm[i] = make_uint4(0u, 0u, 0u, 0u);
            if (gr < n_rows) {
                long gi = (long)gr * K + k0 + aq[i] * 4;
                ra[i] = *(const float4*)&A[gi];
                if (mkind == 0) {
                    rm[i].x = *(const unsigned int*)((const unsigned char*)mask + gi);
                } else if (mkind == 1) {
                    float4 f = *(const float4*)((const float*)mask + gi);
                    rm[i] = make_uint4(__float_as_uint(f.x), __float_as_uint(f.y),
                                       __float_as_uint(f.z), __float_as_uint(f.w));
                } else {
                    rm[i] = *(const uint4*)((const int*)mask + gi);
                }
            }
        }
        #pragma unroll
        for (int i = 0; i < 2; i++)
            rb[i] = *(const float4*)&W[(long)(k0 + bkk[i]) * 64 + bn4[i] * 4];
    };

    auto store_tile = [&](int buf, int k0) {
        #pragma unroll
        for (int i = 0; i < 4; i++) {
            float4 v = ra[i];
            float mv[4];
            if (mkind == 0) {
                unsigned int mw = rm[i].x;
                mv[0] = (mw & 0x000000FFu) ? 2.f : 0.f;
                mv[1] = (mw & 0x0000FF00u) ? 2.f : 0.f;
                mv[2] = (mw & 0x00FF0000u) ? 2.f : 0.f;
                mv[3] = (mw & 0xFF000000u) ? 2.f : 0.f;
            } else {
                mv[0] = rm[i].x ? 2.f : 0.f;
                mv[1] = rm[i].y ? 2.f : 0.f;
                mv[2] = rm[i].z ? 2.f : 0.f;
                mv[3] = rm[i].w ? 2.f : 0.f;
            }
            if (MODE == 1) {
                int kb = k0 + aq[i] * 4;
                v.x = fmaxf(v.x + sb[kb + 0], 0.f);
                v.y = fmaxf(v.y + sb[kb + 1], 0.f);
                v.z = fmaxf(v.z + sb[kb + 2], 0.f);
                v.w = fmaxf(v.w + sb[kb + 3], 0.f);
            }
            int r = arow[i], q4 = aq[i] * 4;
            As[buf][q4 + 0][r] = v.x * mv[0];
            As[buf][q4 + 1][r] = v.y * mv[1];
            As[buf][q4 + 2][r] = v.z * mv[2];
            As[buf][q4 + 3][r] = v.w * mv[3];
        }
        #pragma unroll
        for (int i = 0; i < 2; i++)
            *(float4*)&Bs[buf][bkk[i]][bn4[i] * 4] = rb[i];
    };

    // accumulators packed along n: accp[i][j] = (c[i][2j], c[i][2j+1])
    unsigned long long accp[8][4] = {};
    const int NIT = K / 16;

    load_tile(0);
    store_tile(0, 0);
    __syncthreads();

    for (int it = 0; it < NIT; it++) {
        int cur = it & 1;
        if (it + 1 < NIT) load_tile((it + 1) * 16);

        #pragma unroll
        for (int k = 0; k < 16; k++) {
            float4 a0 = *(const float4*)&As[cur][k][tm * 8];
            float4 a1 = *(const float4*)&As[cur][k][tm * 8 + 4];
            float4 b0 = *(const float4*)&Bs[cur][k][tn * 8];
            float4 b1 = *(const float4*)&Bs[cur][k][tn * 8 + 4];
            unsigned long long bp[4] = {
                pk2(b0.x, b0.y), pk2(b0.z, b0.w),
                pk2(b1.x, b1.y), pk2(b1.z, b1.w)
            };
            float av[8] = {a0.x, a0.y, a0.z, a0.w, a1.x, a1.y, a1.z, a1.w};
            #pragma unroll
            for (int i = 0; i < 8; i++) {
                unsigned long long ad = pk2(av[i], av[i]);
                #pragma unroll
                for (int j = 0; j < 4; j++)
                    accp[i][j] = ffma2(ad, bp[j], accp[i][j]);
            }
        }

        if (it + 1 < NIT) {
            store_tile(cur ^ 1, (it + 1) * 16);
            __syncthreads();
        }
    }

    #pragma unroll
    for (int i = 0; i < 8; i++) {
        int gr = row0 + tm * 8 + i;
        if (gr < n_rows) {
            float c0, c1, c2, c3, c4, c5, c6, c7;
            upk2(c0, c1, accp[i][0]);
            upk2(c2, c3, accp[i][1]);
            upk2(c4, c5, accp[i][2]);
            upk2(c6, c7, accp[i][3]);
            *(float4*)&C[(long)gr * 64 + tn * 8]     = make_float4(c0, c1, c2, c3);
            *(float4*)&C[(long)gr * 64 + tn * 8 + 4] = make_float4(c4, c5, c6, c7);
        }
    }
}

// ---------------------------------------------------------------------------
// Edge scatter: out[dst] += H[src] * w.
// 16 lanes per edge, float4 gather + red.global.add.v4.f32.
// ---------------------------------------------------------------------------
__global__ __launch_bounds__(256) void scatter_kernel(
        const float* __restrict__ H,
        const void* __restrict__ ei_raw,
        const float* __restrict__ ew,
        float* __restrict__ out, int n_edges) {
    int e = blockIdx.x * 16 + (threadIdx.x >> 4);
    if (e >= n_edges) return;
    int c = (threadIdx.x & 15) * 4;
    int s, d;
    if (g_flags[0]) {
        const long long* ei = (const long long*)ei_raw;
        s = (int)__ldg(&ei[e]);
        d = (int)__ldg(&ei[n_edges + e]);
    } else {
        const int* ei = (const int*)ei_raw;
        s = __ldg(&ei[e]);
        d = __ldg(&ei[n_edges + e]);
    }
    float w = __ldg(&ew[e]);
    float4 v = __ldg((const float4*)&H[(long)s * 64 + c]);
    float* o = out + (long)d * 64 + c;
    asm volatile("red.global.add.v4.f32 [%0], {%1, %2, %3, %4};"
                 :: "l"(o), "f"(v.x * w), "f"(v.y * w), "f"(v.z * w), "f"(v.w * w)
                 : "memory");
}

// ---------------------------------------------------------------------------
// inputs: x, edge_index(2xE), edge_weight, W1, b1, W2, b2, mask1, mask2
// ---------------------------------------------------------------------------
extern "C" void kernel_launch(void* const* d_in, const int* in_sizes, int n_in,
                              void* d_out, int out_size) {
    const float* x  = (const float*)d_in[0];
    const void* ei  = d_in[1];
    const float* ew = (const float*)d_in[2];
    const float* W1 = (const float*)d_in[3];
    const float* b1 = (const float*)d_in[4];
    const float* W2 = (const float*)d_in[5];
    const float* b2 = (const float*)d_in[6];
    const void* m1  = d_in[7];
    const void* m2  = d_in[8];
    float* out = (float*)d_out;

    int n_nodes = in_sizes[0] / 384;
    int n_edges = in_sizes[2];

    float *H1, *AGG1, *H2;
    cudaGetSymbolAddress((void**)&H1, g_H1);
    cudaGetSymbolAddress((void**)&AGG1, g_AGG1);
    cudaGetSymbolAddress((void**)&H2, g_H2);

    detect_kernel<<<1, 32>>>((const int*)ei, (const unsigned int*)m1);

    int n4 = n_nodes * 16;
    init_kernel<<<(n4 + 255) / 256, 256>>>(AGG1, out, b2, n4);

    int gb = (n_nodes + 127) / 128;
    int sbk = (n_edges + 15) / 16;
    gemm8x8<384, 0><<<gb, 128>>>(x, m1, W1, nullptr, H1, n_nodes);
    scatter_kernel<<<sbk, 256>>>(H1, ei, ew, AGG1, n_edges);
    gemm8x8<64, 1><<<gb, 128>>>(AGG1, m2, W2, b1, H2, n_nodes);
    scatter_kernel<<<sbk, 256>>>(H2, ei, ew, out, n_edges);
}

// round 9
// speedup vs baseline: 2.2225x; 1.0322x over previous
#include <cuda_runtime.h>
#include <cstdint>

#define D 64
#define NMAX 100000

__device__ float g_H1[NMAX * D];
__device__ float g_AGG1[NMAX * D];
__device__ float g_H2[NMAX * D];

// flags[0]: edge_index is int64 (1) or int32 (0)
// flags[1]: mask elem kind: 0 = uint8, 1 = float32, 2 = int32
__device__ int g_flags[2];

// ---- tf32 helpers -----------------------------------------------------------
__device__ __forceinline__ uint32_t f2tf32(float f) {
    uint32_t r;
    asm("cvt.rna.tf32.f32 %0, %1;" : "=r"(r) : "f"(f));
    return r;
}
__device__ __forceinline__ void mma_tf32(float* c, const uint32_t* a, const uint32_t* b) {
    asm volatile(
        "mma.sync.aligned.m16n8k8.row.col.f32.tf32.tf32.f32 "
        "{%0,%1,%2,%3}, {%4,%5,%6,%7}, {%8,%9}, {%0,%1,%2,%3};"
        : "+f"(c[0]), "+f"(c[1]), "+f"(c[2]), "+f"(c[3])
        : "r"(a[0]), "r"(a[1]), "r"(a[2]), "r"(a[3]), "r"(b[0]), "r"(b[1]));
}

// ---------------------------------------------------------------------------
// Dtype detection — warp-parallel, order-independent predicates.
// ---------------------------------------------------------------------------
__global__ void detect_kernel(const int* __restrict__ ei_words,
                              const unsigned int* __restrict__ mask_words) {
    int lane = threadIdx.x;

    int odd_nonzero = 0;
    #pragma unroll
    for (int i = 0; i < 8; i++) {
        if (ei_words[2 * (lane + i * 32) + 1] != 0) odd_nonzero = 1;
    }
    int is64 = !__any_sync(0xFFFFFFFFu, odd_nonzero);

    int saw_f32 = 0, saw_hi = 0;
    #pragma unroll
    for (int i = 0; i < 128; i++) {
        unsigned int w = mask_words[lane + i * 32];
        if (w == 0x3F800000u) saw_f32 = 1;
        if ((w & 0xFFFFFF00u) != 0) saw_hi = 1;
    }
    int any_f32 = __any_sync(0xFFFFFFFFu, saw_f32);
    int any_hi  = __any_sync(0xFFFFFFFFu, saw_hi);
    if (lane == 0) {
        g_flags[0] = is64;
        g_flags[1] = any_f32 ? 1 : (any_hi ? 0 : 2);
    }
}

// ---------------------------------------------------------------------------
// Init: AGG1 = 0, OUT = broadcast(b2)
// ---------------------------------------------------------------------------
__global__ void init_kernel(float* __restrict__ agg1, float* __restrict__ out,
                            const float* __restrict__ b2, int n4) {
    int i = blockIdx.x * blockDim.x + threadIdx.x;
    if (i >= n4) return;
    ((float4*)agg1)[i] = make_float4(0.f, 0.f, 0.f, 0.f);
    int c4 = i & 15;
    ((float4*)out)[i] = __ldg(&((const float4*)b2)[c4]);
}

// ---------------------------------------------------------------------------
// Fused GEMM, double-buffered, tf32 tensor-core (3-pass split for fp32 accuracy)
//   C[n_rows,64] = f(A) @ W
//   MODE 0: f(a) = mask ? a*2 : 0
//   MODE 1: f(a) = mask ? relu(a + bias[k])*2 : 0
// BM=128, BN=64, BK=16, 256 threads = 8 warps; warp w owns rows [w*16, w*16+16).
// ---------------------------------------------------------------------------
template <int K, int MODE>
__global__ __launch_bounds__(256) void gemm_tc(
        const float* __restrict__ A,
        const void* __restrict__ mask,
        const float* __restrict__ W,
        const float* __restrict__ bias,
        float* __restrict__ C, int n_rows) {
    __shared__ float As[2][128][20];   // [buf][m][k], stride 20: conflict-free frags
    __shared__ float Bs[2][16][72];    // [buf][k][n], stride 72: conflict-free frags
    __shared__ float sb[64];

    const int tid = threadIdx.x;
    const int mkind = g_flags[1];
    if (MODE == 1) {
        if (tid < 64) sb[tid] = bias[tid];
        __syncthreads();
    }

    const int row0 = blockIdx.x * 128;
    const int warp = tid >> 5;
    const int lane = tid & 31;
    const int gid = lane >> 2;    // 0..7
    const int tig = lane & 3;     // 0..3
    const int m0 = warp * 16;

    // A-tile staging: 512 float4 => 2 per thread
    int arow[2], aq[2];
    #pragma unroll
    for (int i = 0; i < 2; i++) {
        int lin = tid + i * 256;
        arow[i] = lin >> 2;        // 0..127
        aq[i]   = lin & 3;
    }
    // W-tile staging: 256 float4 => 1 per thread
    const int bkk = tid >> 4;      // 0..15
    const int bn4 = tid & 15;      // 0..15

    float4 ra[2];
    uint4  rm[2];
    float4 rb;

    auto load_tile = [&](int k0) {
        #pragma unroll
        for (int i = 0; i < 2; i++) {
            int gr = row0 + arow[i];
            ra[i] = make_float4(0.f, 0.f, 0.f, 0.f);
            rm[i] = make_uint4(0u, 0u, 0u, 0u);
            if (gr < n_rows) {
                long gi = (long)gr * K + k0 + aq[i] * 4;
                ra[i] = *(const float4*)&A[gi];
                if (mkind == 0) {
                    rm[i].x = *(const unsigned int*)((const unsigned char*)mask + gi);
                } else if (mkind == 1) {
                    float4 f = *(const float4*)((const float*)mask + gi);
                    rm[i] = make_uint4(__float_as_uint(f.x), __float_as_uint(f.y),
                                       __float_as_uint(f.z), __float_as_uint(f.w));
                } else {
                    rm[i] = *(const uint4*)((const int*)mask + gi);
                }
            }
        }
        rb = *(const float4*)&W[(long)(k0 + bkk) * 64 + bn4 * 4];
    };

    auto store_tile = [&](int buf, int k0) {
        #pragma unroll
        for (int i = 0; i < 2; i++) {
            float4 v = ra[i];
            float mv[4];
            if (mkind == 0) {
                unsigned int mw = rm[i].x;
                mv[0] = (mw & 0x000000FFu) ? 2.f : 0.f;
                mv[1] = (mw & 0x0000FF00u) ? 2.f : 0.f;
                mv[2] = (mw & 0x00FF0000u) ? 2.f : 0.f;
                mv[3] = (mw & 0xFF000000u) ? 2.f : 0.f;
            } else {
                mv[0] = rm[i].x ? 2.f : 0.f;
                mv[1] = rm[i].y ? 2.f : 0.f;
                mv[2] = rm[i].z ? 2.f : 0.f;
                mv[3] = rm[i].w ? 2.f : 0.f;
            }
            if (MODE == 1) {
                int kb = k0 + aq[i] * 4;
                v.x = fmaxf(v.x + sb[kb + 0], 0.f);
                v.y = fmaxf(v.y + sb[kb + 1], 0.f);
                v.z = fmaxf(v.z + sb[kb + 2], 0.f);
                v.w = fmaxf(v.w + sb[kb + 3], 0.f);
            }
            float4 o = make_float4(v.x * mv[0], v.y * mv[1], v.z * mv[2], v.w * mv[3]);
            *(float4*)&As[buf][arow[i]][aq[i] * 4] = o;
        }
        *(float4*)&Bs[buf][bkk][bn4 * 4] = rb;
    };

    float acc[8][4] = {};   // 8 n-tiles of m16n8, 4 regs each
    const int NIT = K / 16;

    load_tile(0);
    store_tile(0, 0);
    __syncthreads();

    for (int it = 0; it < NIT; it++) {
        int cur = it & 1;
        if (it + 1 < NIT) load_tile((it + 1) * 16);

        #pragma unroll
        for (int ks = 0; ks < 2; ks++) {
            int kk = ks * 8;
            // A fragments (m16k8): split into hi/lo tf32
            float f0 = As[cur][m0 + gid    ][kk + tig];
            float f1 = As[cur][m0 + gid + 8][kk + tig];
            float f2 = As[cur][m0 + gid    ][kk + tig + 4];
            float f3 = As[cur][m0 + gid + 8][kk + tig + 4];
            uint32_t ah[4], al[4];
            ah[0] = f2tf32(f0); al[0] = f2tf32(f0 - __uint_as_float(ah[0]));
            ah[1] = f2tf32(f1); al[1] = f2tf32(f1 - __uint_as_float(ah[1]));
            ah[2] = f2tf32(f2); al[2] = f2tf32(f2 - __uint_as_float(ah[2]));
            ah[3] = f2tf32(f3); al[3] = f2tf32(f3 - __uint_as_float(ah[3]));

            #pragma unroll
            for (int nt = 0; nt < 8; nt++) {
                int n0 = nt * 8;
                float g0 = Bs[cur][kk + tig    ][n0 + gid];
                float g1 = Bs[cur][kk + tig + 4][n0 + gid];
                uint32_t bh[2], bl[2];
                bh[0] = f2tf32(g0); bl[0] = f2tf32(g0 - __uint_as_float(bh[0]));
                bh[1] = f2tf32(g1); bl[1] = f2tf32(g1 - __uint_as_float(bh[1]));
                mma_tf32(acc[nt], ah, bh);
                mma_tf32(acc[nt], al, bh);
                mma_tf32(acc[nt], ah, bl);
            }
        }

        if (it + 1 < NIT) {
            store_tile(cur ^ 1, (it + 1) * 16);
            __syncthreads();
        }
    }

    // C store: c0,c1 -> (row, 2*tig / +1); c2,c3 -> (row+8)
    int ra_ = row0 + m0 + gid;
    int rb_ = ra_ + 8;
    #pragma unroll
    for (int nt = 0; nt < 8; nt++) {
        int col = nt * 8 + 2 * tig;
        if (ra_ < n_rows)
            *(float2*)&C[(long)ra_ * 64 + col] = make_float2(acc[nt][0], acc[nt][1]);
        if (rb_ < n_rows)
            *(float2*)&C[(long)rb_ * 64 + col] = make_float2(acc[nt][2], acc[nt][3]);
    }
}

// ---------------------------------------------------------------------------
// Edge scatter: out[dst] += H[src] * w.
// 16 lanes per edge, float4 gather + red.global.add.v4.f32.
// ---------------------------------------------------------------------------
__global__ __launch_bounds__(256) void scatter_kernel(
        const float* __restrict__ H,
        const void* __restrict__ ei_raw,
        const float* __restrict__ ew,
        float* __restrict__ out, int n_edges) {
    int e = blockIdx.x * 16 + (threadIdx.x >> 4);
    if (e >= n_edges) return;
    int c = (threadIdx.x & 15) * 4;
    int s, d;
    if (g_flags[0]) {
        const long long* ei = (const long long*)ei_raw;
        s = (int)__ldg(&ei[e]);
        d = (int)__ldg(&ei[n_edges + e]);
    } else {
        const int* ei = (const int*)ei_raw;
        s = __ldg(&ei[e]);
        d = __ldg(&ei[n_edges + e]);
    }
    float w = __ldg(&ew[e]);
    float4 v = __ldg((const float4*)&H[(long)s * 64 + c]);
    float* o = out + (long)d * 64 + c;
    asm volatile("red.global.add.v4.f32 [%0], {%1, %2, %3, %4};"
                 :: "l"(o), "f"(v.x * w), "f"(v.y * w), "f"(v.z * w), "f"(v.w * w)
                 : "memory");
}

// ---------------------------------------------------------------------------
// inputs: x, edge_index(2xE), edge_weight, W1, b1, W2, b2, mask1, mask2
// ---------------------------------------------------------------------------
extern "C" void kernel_launch(void* const* d_in, const int* in_sizes, int n_in,
                              void* d_out, int out_size) {
    const float* x  = (const float*)d_in[0];
    const void* ei  = d_in[1];
    const float* ew = (const float*)d_in[2];
    const float* W1 = (const float*)d_in[3];
    const float* b1 = (const float*)d_in[4];
    const float* W2 = (const float*)d_in[5];
    const float* b2 = (const float*)d_in[6];
    const void* m1  = d_in[7];
    const void* m2  = d_in[8];
    float* out = (float*)d_out;

    int n_nodes = in_sizes[0] / 384;
    int n_edges = in_sizes[2];

    float *H1, *AGG1, *H2;
    cudaGetSymbolAddress((void**)&H1, g_H1);
    cudaGetSymbolAddress((void**)&AGG1, g_AGG1);
    cudaGetSymbolAddress((void**)&H2, g_H2);

    detect_kernel<<<1, 32>>>((const int*)ei, (const unsigned int*)m1);

    int n4 = n_nodes * 16;
    init_kernel<<<(n4 + 255) / 256, 256>>>(AGG1, out, b2, n4);

    int gb = (n_nodes + 127) / 128;
    int sbk = (n_edges + 15) / 16;
    gemm_tc<384, 0><<<gb, 256>>>(x, m1, W1, nullptr, H1, n_nodes);
    scatter_kernel<<<sbk, 256>>>(H1, ei, ew, AGG1, n_edges);
    gemm_tc<64, 1><<<gb, 256>>>(AGG1, m2, W2, b1, H2, n_nodes);
    scatter_kernel<<<sbk, 256>>>(H2, ei, ew, out, n_edges);
}